// round 13
// baseline (speedup 1.0000x reference)
#include <cuda_runtime.h>
#include <cuda_bf16.h>
#include <math.h>
#include <stdint.h>

// ---------------- problem constants ----------------
constexpr int   BN      = 8192;
constexpr int   DD      = 256;
constexpr int   NS      = 64;
constexpr float INV_TAU = 1.0f / 0.07f;
constexpr float MARGIN  = 0.2f;

// ---------------- device scratch ----------------
__device__ __align__(16) __nv_bfloat16 g_Abf[(size_t)BN * DD];
__device__ __align__(16) __nv_bfloat16 g_Bbf[(size_t)BN * DD];

__device__ float g_rowexp[BN];
__device__ float g_colexp[BN];
__device__ float g_rowsum[BN];
__device__ float g_rowsame[BN];
__device__ float g_diag[BN];
__device__ float g_cnt[NS];
__device__ int   g_cnti[NS];
__device__ float g_segv[NS];
__device__ float g_segt[NS];
__device__ float g_tri[2];
__device__ int   g_done;

__device__ float g_Tall[DD];        // total column sum of T
__device__ int   g_off[NS];
__device__ int   g_fill[NS];
__device__ int   g_perm[BN];        // rows grouped by species

// ---------------- setup: histogram + offsets + zero small scratch (1 block) ----
__global__ void setup_kernel(const int* __restrict__ ids) {
    __shared__ int hist[NS];
    const int tid = threadIdx.x;         // 1024 threads
    if (tid < NS) hist[tid] = 0;
    __syncthreads();
    #pragma unroll
    for (int t = 0; t < BN / 1024; t++)
        atomicAdd(&hist[ids[tid + t * 1024]], 1);
    __syncthreads();
    if (tid == 0) {
        int run = 0;
        for (int c = 0; c < NS; c++) {
            g_off[c] = run;
            int h = hist[c];
            g_cnti[c] = h;
            g_cnt[c] = (float)h;
            run += h;
        }
        g_done = 0;
        g_tri[0] = 0.f; g_tri[1] = 0.f;
    }
    if (tid < NS) {
        g_fill[tid] = 0;
        g_segv[tid] = 0.f;
        g_segt[tid] = 0.f;
    }
    if (tid < DD) g_Tall[tid] = 0.f;
}

// ---------------- prep: fp32->bf16, exact diag, scatter, Tall, zero stats -----
__global__ void prep_kernel(const float* __restrict__ S,
                            const float* __restrict__ T,
                            const int* __restrict__ ids) {
    __shared__ float sh_tall[DD];
    const int tid  = threadIdx.x;
    const int warp = tid >> 5;
    const int lane = tid & 31;
    const int row  = blockIdx.x * 8 + warp;
    if (tid < DD) sh_tall[tid] = 0.f;
    __syncthreads();

    const float4* s4 = (const float4*)(S + (size_t)row * DD);
    const float4* t4 = (const float4*)(T + (size_t)row * DD);
    float4 s0 = s4[lane * 2], s1 = s4[lane * 2 + 1];
    float4 t0 = t4[lane * 2], t1 = t4[lane * 2 + 1];

    __align__(16) __nv_bfloat162 sb[4];
    __align__(16) __nv_bfloat162 tb[4];
    sb[0] = __floats2bfloat162_rn(s0.x, s0.y);
    sb[1] = __floats2bfloat162_rn(s0.z, s0.w);
    sb[2] = __floats2bfloat162_rn(s1.x, s1.y);
    sb[3] = __floats2bfloat162_rn(s1.z, s1.w);
    tb[0] = __floats2bfloat162_rn(t0.x, t0.y);
    tb[1] = __floats2bfloat162_rn(t0.z, t0.w);
    tb[2] = __floats2bfloat162_rn(t1.x, t1.y);
    tb[3] = __floats2bfloat162_rn(t1.z, t1.w);
    *(uint4*)&g_Abf[(size_t)row * DD + lane * 8] = *(const uint4*)sb;
    *(uint4*)&g_Bbf[(size_t)row * DD + lane * 8] = *(const uint4*)tb;

    // Tall partial: this thread holds dims [8*lane, 8*lane+8) of its row
    const int d0 = lane * 8;
    atomicAdd(&sh_tall[d0 + 0], t0.x); atomicAdd(&sh_tall[d0 + 1], t0.y);
    atomicAdd(&sh_tall[d0 + 2], t0.z); atomicAdd(&sh_tall[d0 + 3], t0.w);
    atomicAdd(&sh_tall[d0 + 4], t1.x); atomicAdd(&sh_tall[d0 + 5], t1.y);
    atomicAdd(&sh_tall[d0 + 6], t1.z); atomicAdd(&sh_tall[d0 + 7], t1.w);

    float dot = s0.x * t0.x + s0.y * t0.y + s0.z * t0.z + s0.w * t0.w
              + s1.x * t1.x + s1.y * t1.y + s1.z * t1.z + s1.w * t1.w;
    #pragma unroll
    for (int o = 16; o > 0; o >>= 1)
        dot += __shfl_xor_sync(0xffffffffu, dot, o);

    if (lane == 0) {
        g_diag[row] = dot;
        g_rowexp[row]  = 0.f;
        g_colexp[row]  = 0.f;
        g_rowsame[row] = 0.f;
        int id = ids[row];
        int pos = g_off[id] + atomicAdd(&g_fill[id], 1);
        g_perm[pos] = row;
    }
    __syncthreads();
    if (tid < DD) atomicAdd(&g_Tall[tid], sh_tall[tid]);
}

// ---------------- PTX helpers ----------------
__device__ __forceinline__ uint32_t smem_u32(const void* p) {
    uint32_t a;
    asm("{ .reg .u64 t; cvta.to.shared.u64 t, %1; cvt.u32.u64 %0, t; }"
        : "=r"(a) : "l"(p));
    return a;
}
__device__ __forceinline__ void cp16(uint32_t dst, const void* src) {
    asm volatile("cp.async.cg.shared.global [%0], [%1], 16;" :: "r"(dst), "l"(src));
}
template<int N> __device__ __forceinline__ void cp_wait() {
    asm volatile("cp.async.wait_group %0;" :: "n"(N) : "memory");
}
__device__ __forceinline__ void ldsm_x4(uint32_t* r, uint32_t addr) {
    asm volatile("ldmatrix.sync.aligned.m8n8.x4.shared.b16 {%0,%1,%2,%3}, [%4];"
                 : "=r"(r[0]), "=r"(r[1]), "=r"(r[2]), "=r"(r[3]) : "r"(addr));
}
__device__ __forceinline__ void mma16816(float* d, const uint32_t* a, const uint32_t* b) {
    asm volatile(
        "mma.sync.aligned.m16n8k16.row.col.f32.bf16.bf16.f32 "
        "{%0,%1,%2,%3}, {%4,%5,%6,%7}, {%8,%9}, {%0,%1,%2,%3};"
        : "+f"(d[0]), "+f"(d[1]), "+f"(d[2]), "+f"(d[3])
        : "r"(a[0]), "r"(a[1]), "r"(a[2]), "r"(a[3]), "r"(b[0]), "r"(b[1]));
}
// SW128 swizzle within a [64 rows x 128B] chunk
__device__ __forceinline__ uint32_t swz(int r, int q) {
    return (uint32_t)(r * 128 + ((q ^ (r & 7)) << 4));
}

// blockexp smem layout (dynamic)
constexpr int SB_OFF    = 32768;
constexpr int RA_OFF    = 65536;               // 64 ints
constexpr int RB_OFF    = RA_OFF + 256;        // 64 ints
constexpr int REXP_OFF  = RB_OFF + 256;        // 64 floats
constexpr int CEXP_OFF  = REXP_OFF + 256;      // 64 floats
constexpr int RSAME_OFF = CEXP_OFF + 256;      // 64 floats
constexpr int TALL_OFF  = RSAME_OFF + 256;     // 256 floats
constexpr int SMEM_BE   = TALL_OFF + 1024;     // 67840 bytes

// ---------------- blockexp: same-species 64x64 exp blocks + rsame + rsum ------
// grid: (16, NS); 128 threads (4 warps)
__global__ void __launch_bounds__(128)
blockexp_kernel() {
    const int c  = blockIdx.y;
    const int x  = blockIdx.x;
    const int mt = x & 3;
    const int nt = x >> 2;
    const int n_c = g_cnti[c];
    if (mt * 64 >= n_c || nt * 64 >= n_c) return;
    const int o = g_off[c];
    const int mrem = n_c - mt * 64;
    const int nrem = n_c - nt * 64;

    extern __shared__ char smem[];
    const uint32_t sbase = smem_u32(smem);
    int*   s_ra    = (int*)(smem + RA_OFF);
    int*   s_rb    = (int*)(smem + RB_OFF);
    float* s_rexp  = (float*)(smem + REXP_OFF);
    float* s_cexp  = (float*)(smem + CEXP_OFF);
    float* s_rsame = (float*)(smem + RSAME_OFF);
    float* s_tall  = (float*)(smem + TALL_OFF);

    const int tid  = threadIdx.x;
    const int wid  = tid >> 5;
    const int lane = tid & 31;

    if (tid < 64) {
        int r = mt * 64 + tid;
        s_ra[tid] = g_perm[o + min(r, n_c - 1)];
        s_rexp[tid] = 0.f; s_rsame[tid] = 0.f;
    } else {
        int t = tid - 64;
        int r = nt * 64 + t;
        s_rb[t] = g_perm[o + min(r, n_c - 1)];
        s_cexp[t] = 0.f;
    }
    __syncthreads();

    // gather load, two commit groups (K-chunks 0-1, then 2-3); Tall in group 0
    if (nt == 0 && tid < 64)
        cp16(sbase + (TALL_OFF - 0) + tid * 16, &g_Tall[tid * 4]);
    #pragma unroll
    for (int g = 0; g < 2; g++) {
        #pragma unroll
        for (int h = 0; h < 8; h++) {
            int f  = tid + h * 128;          // 0..1023
            int r  = f >> 4;                 // 0..63
            int qq = f & 15;                 // 0..15
            int kc = g * 2 + (qq >> 3);
            int q7 = qq & 7;
            uint32_t sw = (uint32_t)(kc * 8192) + swz(r, q7);
            cp16(sbase + sw,
                 &g_Abf[(size_t)s_ra[r] * DD + kc * 64 + q7 * 8]);
            cp16(sbase + SB_OFF + sw,
                 &g_Bbf[(size_t)s_rb[r] * DD + kc * 64 + q7 * 8]);
        }
        asm volatile("cp.async.commit_group;");
    }

    // fragment base offsets (within a chunk); addr(ks) = base ^ ((ks&3)<<5)
    uint32_t aD, bD[4];
    aD = swz(wid * 16 + (lane & 15), lane >> 4);
    #pragma unroll
    for (int np = 0; np < 4; np++)
        bD[np] = swz(np * 16 + ((lane >> 4) & 1) * 8 + (lane & 7),
                     (lane >> 3) & 1);

    float acc[8][4];
    #pragma unroll
    for (int nt2 = 0; nt2 < 8; nt2++)
        #pragma unroll
        for (int cc = 0; cc < 4; cc++) acc[nt2][cc] = 0.f;

    cp_wait<1>();
    __syncthreads();
    #pragma unroll
    for (int ks = 0; ks < 8; ks++) {
        const uint32_t base = sbase + (uint32_t)((ks >> 2) * 8192);
        const uint32_t kx   = (uint32_t)(ks & 3) << 5;
        uint32_t a[4], b[8][2];
        ldsm_x4(a, base + (aD ^ kx));
        #pragma unroll
        for (int np = 0; np < 4; np++)
            ldsm_x4(&b[2 * np][0], base + SB_OFF + (bD[np] ^ kx));
        #pragma unroll
        for (int nt2 = 0; nt2 < 8; nt2++)
            mma16816(acc[nt2], a, b[nt2]);
    }
    cp_wait<0>();
    __syncthreads();
    #pragma unroll
    for (int ks = 8; ks < 16; ks++) {
        const uint32_t base = sbase + (uint32_t)((ks >> 2) * 8192);
        const uint32_t kx   = (uint32_t)(ks & 3) << 5;
        uint32_t a[4], b[8][2];
        ldsm_x4(a, base + (aD ^ kx));
        #pragma unroll
        for (int np = 0; np < 4; np++)
            ldsm_x4(&b[2 * np][0], base + SB_OFF + (bD[np] ^ kx));
        #pragma unroll
        for (int nt2 = 0; nt2 < 8; nt2++)
            mma16816(acc[nt2], a, b[nt2]);
    }

    // ---- rsum for this tile's A-rows (nt==0 tiles only): dot(bf16 row, Tall)
    if (nt == 0) {
        const int r  = tid >> 1;         // 0..63
        const int hf = tid & 1;          // half of dims
        float partial = 0.f;
        #pragma unroll
        for (int cell = 0; cell < 16; cell++) {
            int d0 = hf * 128 + cell * 8;
            int kc = d0 >> 6;
            int q7 = (d0 & 63) >> 3;
            uint4 v = *(const uint4*)(smem + kc * 8192 + swz(r, q7));
            const __nv_bfloat162* p = (const __nv_bfloat162*)&v;
            #pragma unroll
            for (int i = 0; i < 4; i++) {
                float2 f2 = __bfloat1622float2(p[i]);
                partial += f2.x * s_tall[d0 + 2 * i]
                         + f2.y * s_tall[d0 + 2 * i + 1];
            }
        }
        partial += __shfl_xor_sync(0xffffffffu, partial, 1);
        if (hf == 0 && r < mrem) g_rowsum[s_ra[r]] = partial;
    }

    // epilogue: exp + raw sums over valid same-species elements, exact diag
    #pragma unroll
    for (int h = 0; h < 2; h++) {
        const int rloc = wid * 16 + (lane >> 2) + 8 * h;
        const bool rvalid = rloc < mrem;
        const int gr = s_ra[rloc];
        const float dval = g_diag[gr];
        float re = 0.f, rsm = 0.f;
        #pragma unroll
        for (int nt2 = 0; nt2 < 8; nt2++) {
            #pragma unroll
            for (int cc = 0; cc < 2; cc++) {
                int cloc = nt2 * 8 + (lane & 3) * 2 + cc;
                if (rvalid && cloc < nrem) {
                    float s = acc[nt2][2 * h + cc];
                    if (gr == s_rb[cloc]) s = dval;
                    rsm += s;
                    float e = __expf((s - 1.0f) * INV_TAU);
                    re += e;
                    atomicAdd(&s_cexp[cloc], e);
                }
            }
        }
        if (rvalid) {
            atomicAdd(&s_rexp[rloc], re);
            atomicAdd(&s_rsame[rloc], rsm);
        }
    }
    __syncthreads();

    if (tid < 64) {
        if (tid < mrem) {
            atomicAdd(&g_rowexp[s_ra[tid]],  s_rexp[tid]);
            atomicAdd(&g_rowsame[s_ra[tid]], s_rsame[tid]);
        }
    } else {
        int t = tid - 64;
        if (t < nrem) atomicAdd(&g_colexp[s_rb[t]], s_cexp[t]);
    }
}

// ---------------- final: per-row CE + triplet + segments + combine ------------
__global__ void final_kernel(const int* __restrict__ ids,
                             float* __restrict__ out) {
    __shared__ float sh_segv[NS];
    __shared__ float sh_segt[NS];
    __shared__ bool  sh_last;
    const int tid = threadIdx.x;
    if (tid < NS) { sh_segv[tid] = 0.f; sh_segt[tid] = 0.f; }
    __syncthreads();

    const int i = blockIdx.x * blockDim.x + tid;   // grid 32 x 256
    const int id = ids[i];
    float dg = g_diag[i];
    float dl = dg * INV_TAU;
    float cev = logf(g_rowexp[i]) + INV_TAU - dl;
    float cet = logf(g_colexp[i]) + INV_TAU - dl;
    atomicAdd(&sh_segv[id], cev);
    atomicAdd(&sh_segt[id], cet);

    float cnt = g_cnt[id];
    float pos_cnt = cnt - 1.0f;
    float neg_cnt = (float)BN - cnt;
    float pos_mean = (g_rowsame[i] - dg) / fmaxf(pos_cnt, 1.0f);
    float neg_mean = (g_rowsum[i] - g_rowsame[i]) / fmaxf(neg_cnt, 1.0f);
    float tri = fmaxf(neg_mean - pos_mean + MARGIN, 0.0f);
    bool valid = (pos_cnt > 0.0f) && (neg_cnt > 0.0f);
    float tri_v = valid ? tri : 0.0f;
    float tri_n = valid ? 1.0f : 0.0f;
    #pragma unroll
    for (int o = 16; o > 0; o >>= 1) {
        tri_v += __shfl_xor_sync(0xffffffffu, tri_v, o);
        tri_n += __shfl_xor_sync(0xffffffffu, tri_n, o);
    }
    if ((tid & 31) == 0) {
        atomicAdd(&g_tri[0], tri_v);
        atomicAdd(&g_tri[1], tri_n);
    }
    __syncthreads();
    if (tid < NS) {
        atomicAdd(&g_segv[tid], sh_segv[tid]);
        atomicAdd(&g_segt[tid], sh_segt[tid]);
    }

    __threadfence();
    __syncthreads();
    if (tid == 0)
        sh_last = (atomicAdd(&g_done, 1) == (int)gridDim.x - 1);
    __syncthreads();
    if (sh_last && tid == 0) {
        __threadfence();
        float Ssum = 0.f, Nval = 0.f;
        for (int c = 0; c < NS; c++) {
            float cnt2 = g_cnt[c];
            if (cnt2 >= 2.0f) {
                Ssum += (g_segv[c] + g_segt[c]) / (2.0f * cnt2);
                Nval += 1.0f;
            }
        }
        float loss_infonce = Ssum / fmaxf(Nval, 1.0f);
        float loss_triplet = g_tri[0] / fmaxf(g_tri[1], 1.0f);
        out[0] = loss_infonce + loss_triplet;
    }
}

extern "C" void kernel_launch(void* const* d_in, const int* in_sizes, int n_in,
                              void* d_out, int out_size) {
    const float* species = (const float*)d_in[0];
    const float* text    = (const float*)d_in[1];
    const int*   ids     = (const int*)d_in[2];
    float* out = (float*)d_out;

    cudaFuncSetAttribute(blockexp_kernel,
                         cudaFuncAttributeMaxDynamicSharedMemorySize, SMEM_BE);

    setup_kernel<<<1, 1024>>>(ids);
    prep_kernel<<<BN / 8, 256>>>(species, text, ids);
    blockexp_kernel<<<dim3(16, NS), 128, SMEM_BE>>>();
    final_kernel<<<BN / 256, 256>>>(ids, out);
}

// round 14
// speedup vs baseline: 1.0871x; 1.0871x over previous
#include <cuda_runtime.h>
#include <cuda_bf16.h>
#include <math.h>
#include <stdint.h>

// ---------------- problem constants ----------------
constexpr int   BN      = 8192;
constexpr int   DD      = 256;
constexpr int   NS      = 64;
constexpr float INV_TAU = 1.0f / 0.07f;
constexpr float MARGIN  = 0.2f;

// ---------------- device scratch ----------------
__device__ __align__(16) __nv_bfloat16 g_Abf[(size_t)BN * DD];
__device__ __align__(16) __nv_bfloat16 g_Bbf[(size_t)BN * DD];

__device__ float g_rowexp[BN];
__device__ float g_colexp[BN];
__device__ float g_rowsum[BN];
__device__ float g_rowsame[BN];
__device__ float g_diag[BN];
__device__ float g_cnt[NS];
__device__ int   g_cnti[NS];
__device__ float g_segv[NS];
__device__ float g_segt[NS];
__device__ float g_tri[2];
__device__ int   g_done;

__device__ float g_Tall[DD];        // total column sum of T
__device__ int   g_off[NS];
__device__ int   g_fill[NS];
__device__ int   g_perm[BN];        // rows grouped by species

// ---------------- setup: histogram + offsets + zero small scratch (1 block) ----
__global__ void setup_kernel(const int* __restrict__ ids) {
    __shared__ int hist[NS];
    const int tid = threadIdx.x;         // 1024 threads
    if (tid < NS) hist[tid] = 0;
    __syncthreads();
    #pragma unroll
    for (int t = 0; t < BN / 1024; t++)
        atomicAdd(&hist[ids[tid + t * 1024]], 1);
    __syncthreads();
    if (tid == 0) {
        int run = 0;
        for (int c = 0; c < NS; c++) {
            g_off[c] = run;
            int h = hist[c];
            g_cnti[c] = h;
            g_cnt[c] = (float)h;
            run += h;
        }
        g_done = 0;
        g_tri[0] = 0.f; g_tri[1] = 0.f;
    }
    if (tid < NS) {
        g_fill[tid] = 0;
        g_segv[tid] = 0.f;
        g_segt[tid] = 0.f;
    }
    if (tid < DD) g_Tall[tid] = 0.f;
}

// ---------------- prep: fp32->bf16, exact diag, scatter, Tall, zero stats -----
__global__ void prep_kernel(const float* __restrict__ S,
                            const float* __restrict__ T,
                            const int* __restrict__ ids) {
    __shared__ float sh_tall[DD];
    const int tid  = threadIdx.x;
    const int warp = tid >> 5;
    const int lane = tid & 31;
    const int row  = blockIdx.x * 8 + warp;
    if (tid < DD) sh_tall[tid] = 0.f;
    __syncthreads();

    const float4* s4 = (const float4*)(S + (size_t)row * DD);
    const float4* t4 = (const float4*)(T + (size_t)row * DD);
    float4 s0 = s4[lane * 2], s1 = s4[lane * 2 + 1];
    float4 t0 = t4[lane * 2], t1 = t4[lane * 2 + 1];

    __align__(16) __nv_bfloat162 sb[4];
    __align__(16) __nv_bfloat162 tb[4];
    sb[0] = __floats2bfloat162_rn(s0.x, s0.y);
    sb[1] = __floats2bfloat162_rn(s0.z, s0.w);
    sb[2] = __floats2bfloat162_rn(s1.x, s1.y);
    sb[3] = __floats2bfloat162_rn(s1.z, s1.w);
    tb[0] = __floats2bfloat162_rn(t0.x, t0.y);
    tb[1] = __floats2bfloat162_rn(t0.z, t0.w);
    tb[2] = __floats2bfloat162_rn(t1.x, t1.y);
    tb[3] = __floats2bfloat162_rn(t1.z, t1.w);
    *(uint4*)&g_Abf[(size_t)row * DD + lane * 8] = *(const uint4*)sb;
    *(uint4*)&g_Bbf[(size_t)row * DD + lane * 8] = *(const uint4*)tb;

    // Tall partial: this thread holds dims [8*lane, 8*lane+8) of its row
    const int d0 = lane * 8;
    atomicAdd(&sh_tall[d0 + 0], t0.x); atomicAdd(&sh_tall[d0 + 1], t0.y);
    atomicAdd(&sh_tall[d0 + 2], t0.z); atomicAdd(&sh_tall[d0 + 3], t0.w);
    atomicAdd(&sh_tall[d0 + 4], t1.x); atomicAdd(&sh_tall[d0 + 5], t1.y);
    atomicAdd(&sh_tall[d0 + 6], t1.z); atomicAdd(&sh_tall[d0 + 7], t1.w);

    float dot = s0.x * t0.x + s0.y * t0.y + s0.z * t0.z + s0.w * t0.w
              + s1.x * t1.x + s1.y * t1.y + s1.z * t1.z + s1.w * t1.w;
    #pragma unroll
    for (int o = 16; o > 0; o >>= 1)
        dot += __shfl_xor_sync(0xffffffffu, dot, o);

    if (lane == 0) {
        g_diag[row] = dot;
        g_rowexp[row]  = 0.f;
        g_colexp[row]  = 0.f;
        g_rowsame[row] = 0.f;
        int id = ids[row];
        int pos = g_off[id] + atomicAdd(&g_fill[id], 1);
        g_perm[pos] = row;
    }
    __syncthreads();
    if (tid < DD) atomicAdd(&g_Tall[tid], sh_tall[tid]);
}

// ---------------- PTX helpers ----------------
__device__ __forceinline__ uint32_t smem_u32(const void* p) {
    uint32_t a;
    asm("{ .reg .u64 t; cvta.to.shared.u64 t, %1; cvt.u32.u64 %0, t; }"
        : "=r"(a) : "l"(p));
    return a;
}
__device__ __forceinline__ void cp16(uint32_t dst, const void* src) {
    asm volatile("cp.async.cg.shared.global [%0], [%1], 16;" :: "r"(dst), "l"(src));
}
template<int N> __device__ __forceinline__ void cp_wait() {
    asm volatile("cp.async.wait_group %0;" :: "n"(N) : "memory");
}
__device__ __forceinline__ void ldsm_x4(uint32_t* r, uint32_t addr) {
    asm volatile("ldmatrix.sync.aligned.m8n8.x4.shared.b16 {%0,%1,%2,%3}, [%4];"
                 : "=r"(r[0]), "=r"(r[1]), "=r"(r[2]), "=r"(r[3]) : "r"(addr));
}
__device__ __forceinline__ void mma16816(float* d, const uint32_t* a, const uint32_t* b) {
    asm volatile(
        "mma.sync.aligned.m16n8k16.row.col.f32.bf16.bf16.f32 "
        "{%0,%1,%2,%3}, {%4,%5,%6,%7}, {%8,%9}, {%0,%1,%2,%3};"
        : "+f"(d[0]), "+f"(d[1]), "+f"(d[2]), "+f"(d[3])
        : "r"(a[0]), "r"(a[1]), "r"(a[2]), "r"(a[3]), "r"(b[0]), "r"(b[1]));
}
// SW128 swizzle within a [64 rows x 128B] chunk
__device__ __forceinline__ uint32_t swz(int r, int q) {
    return (uint32_t)(r * 128 + ((q ^ (r & 7)) << 4));
}

// blockexp smem layout (dynamic)
constexpr int SB_OFF    = 32768;
constexpr int RA_OFF    = 65536;               // 64 ints
constexpr int RB_OFF    = RA_OFF + 256;        // 64 ints
constexpr int REXP_OFF  = RB_OFF + 256;        // 64 floats
constexpr int CEXP_OFF  = REXP_OFF + 256;      // 64 floats
constexpr int RSAME_OFF = CEXP_OFF + 256;      // 64 floats
constexpr int TALL_OFF  = RSAME_OFF + 256;     // 256 floats
constexpr int SMEM_BE   = TALL_OFF + 1024;     // 67840 bytes

// ---------------- blockexp: same-species 64x64 exp blocks + rsame + rsum ------
// grid: (16, NS); 128 threads (4 warps)
__global__ void __launch_bounds__(128)
blockexp_kernel() {
    const int c  = blockIdx.y;
    const int x  = blockIdx.x;
    const int mt = x & 3;
    const int nt = x >> 2;
    const int n_c = g_cnti[c];
    if (mt * 64 >= n_c || nt * 64 >= n_c) return;
    const int o = g_off[c];
    const int mrem = n_c - mt * 64;
    const int nrem = n_c - nt * 64;

    extern __shared__ char smem[];
    const uint32_t sbase = smem_u32(smem);
    int*   s_ra    = (int*)(smem + RA_OFF);
    int*   s_rb    = (int*)(smem + RB_OFF);
    float* s_rexp  = (float*)(smem + REXP_OFF);
    float* s_cexp  = (float*)(smem + CEXP_OFF);
    float* s_rsame = (float*)(smem + RSAME_OFF);
    float* s_tall  = (float*)(smem + TALL_OFF);

    const int tid  = threadIdx.x;
    const int wid  = tid >> 5;
    const int lane = tid & 31;

    if (tid < 64) {
        int r = mt * 64 + tid;
        s_ra[tid] = g_perm[o + min(r, n_c - 1)];
        s_rexp[tid] = 0.f; s_rsame[tid] = 0.f;
    } else {
        int t = tid - 64;
        int r = nt * 64 + t;
        s_rb[t] = g_perm[o + min(r, n_c - 1)];
        s_cexp[t] = 0.f;
    }
    __syncthreads();

    // gather load, two commit groups (K-chunks 0-1, then 2-3); Tall in group 0
    if (nt == 0 && tid < 64)
        cp16(sbase + TALL_OFF + tid * 16, &g_Tall[tid * 4]);
    #pragma unroll
    for (int g = 0; g < 2; g++) {
        #pragma unroll
        for (int h = 0; h < 8; h++) {
            int f  = tid + h * 128;          // 0..1023
            int r  = f >> 4;                 // 0..63
            int qq = f & 15;                 // 0..15
            int kc = g * 2 + (qq >> 3);
            int q7 = qq & 7;
            uint32_t sw = (uint32_t)(kc * 8192) + swz(r, q7);
            cp16(sbase + sw,
                 &g_Abf[(size_t)s_ra[r] * DD + kc * 64 + q7 * 8]);
            cp16(sbase + SB_OFF + sw,
                 &g_Bbf[(size_t)s_rb[r] * DD + kc * 64 + q7 * 8]);
        }
        asm volatile("cp.async.commit_group;");
    }

    // fragment base offsets (within a chunk); addr(ks) = base ^ ((ks&3)<<5)
    uint32_t aD, bD[4];
    aD = swz(wid * 16 + (lane & 15), lane >> 4);
    #pragma unroll
    for (int np = 0; np < 4; np++)
        bD[np] = swz(np * 16 + ((lane >> 4) & 1) * 8 + (lane & 7),
                     (lane >> 3) & 1);

    float acc[8][4];
    #pragma unroll
    for (int nt2 = 0; nt2 < 8; nt2++)
        #pragma unroll
        for (int cc = 0; cc < 4; cc++) acc[nt2][cc] = 0.f;

    cp_wait<1>();
    __syncthreads();
    #pragma unroll
    for (int ks = 0; ks < 8; ks++) {
        const uint32_t base = sbase + (uint32_t)((ks >> 2) * 8192);
        const uint32_t kx   = (uint32_t)(ks & 3) << 5;
        uint32_t a[4], b[8][2];
        ldsm_x4(a, base + (aD ^ kx));
        #pragma unroll
        for (int np = 0; np < 4; np++)
            ldsm_x4(&b[2 * np][0], base + SB_OFF + (bD[np] ^ kx));
        #pragma unroll
        for (int nt2 = 0; nt2 < 8; nt2++)
            mma16816(acc[nt2], a, b[nt2]);
    }
    cp_wait<0>();
    __syncthreads();
    #pragma unroll
    for (int ks = 8; ks < 16; ks++) {
        const uint32_t base = sbase + (uint32_t)((ks >> 2) * 8192);
        const uint32_t kx   = (uint32_t)(ks & 3) << 5;
        uint32_t a[4], b[8][2];
        ldsm_x4(a, base + (aD ^ kx));
        #pragma unroll
        for (int np = 0; np < 4; np++)
            ldsm_x4(&b[2 * np][0], base + SB_OFF + (bD[np] ^ kx));
        #pragma unroll
        for (int nt2 = 0; nt2 < 8; nt2++)
            mma16816(acc[nt2], a, b[nt2]);
    }

    // ---- rsum for this tile's A-rows (nt==0 tiles only): dot(bf16 row, Tall)
    if (nt == 0) {
        const int r  = tid >> 1;         // 0..63
        const int hf = tid & 1;          // half of dims
        float partial = 0.f;
        #pragma unroll
        for (int cell = 0; cell < 16; cell++) {
            int d0 = hf * 128 + cell * 8;
            int kc = d0 >> 6;
            int q7 = (d0 & 63) >> 3;
            uint4 v = *(const uint4*)(smem + kc * 8192 + swz(r, q7));
            const __nv_bfloat162* p = (const __nv_bfloat162*)&v;
            #pragma unroll
            for (int i = 0; i < 4; i++) {
                float2 f2 = __bfloat1622float2(p[i]);
                partial += f2.x * s_tall[d0 + 2 * i]
                         + f2.y * s_tall[d0 + 2 * i + 1];
            }
        }
        partial += __shfl_xor_sync(0xffffffffu, partial, 1);
        if (hf == 0 && r < mrem) g_rowsum[s_ra[r]] = partial;
    }

    // epilogue: exp + raw sums over valid same-species elements, exact diag
    #pragma unroll
    for (int h = 0; h < 2; h++) {
        const int rloc = wid * 16 + (lane >> 2) + 8 * h;
        const bool rvalid = rloc < mrem;
        const int gr = s_ra[rloc];
        const float dval = g_diag[gr];
        float re = 0.f, rsm = 0.f;
        #pragma unroll
        for (int nt2 = 0; nt2 < 8; nt2++) {
            #pragma unroll
            for (int cc = 0; cc < 2; cc++) {
                int cloc = nt2 * 8 + (lane & 3) * 2 + cc;
                if (rvalid && cloc < nrem) {
                    float s = acc[nt2][2 * h + cc];
                    if (gr == s_rb[cloc]) s = dval;
                    rsm += s;
                    float e = __expf((s - 1.0f) * INV_TAU);
                    re += e;
                    atomicAdd(&s_cexp[cloc], e);
                }
            }
        }
        if (rvalid) {
            atomicAdd(&s_rexp[rloc], re);
            atomicAdd(&s_rsame[rloc], rsm);
        }
    }
    __syncthreads();

    if (tid < 64) {
        if (tid < mrem) {
            atomicAdd(&g_rowexp[s_ra[tid]],  s_rexp[tid]);
            atomicAdd(&g_rowsame[s_ra[tid]], s_rsame[tid]);
        }
    } else {
        int t = tid - 64;
        if (t < nrem) atomicAdd(&g_colexp[s_rb[t]], s_cexp[t]);
    }
}

// ---------------- final: per-row CE + triplet + segments + parallel combine ---
__global__ void final_kernel(const int* __restrict__ ids,
                             float* __restrict__ out) {
    __shared__ float sh_segv[NS];
    __shared__ float sh_segt[NS];
    __shared__ float sh_red[NS];
    __shared__ bool  sh_last;
    const int tid = threadIdx.x;
    if (tid < NS) { sh_segv[tid] = 0.f; sh_segt[tid] = 0.f; }
    __syncthreads();

    const int i = blockIdx.x * blockDim.x + tid;   // grid 32 x 256
    const int id = ids[i];
    float dg = g_diag[i];
    float dl = dg * INV_TAU;
    float cev = __logf(g_rowexp[i]) + INV_TAU - dl;
    float cet = __logf(g_colexp[i]) + INV_TAU - dl;
    atomicAdd(&sh_segv[id], cev);
    atomicAdd(&sh_segt[id], cet);

    float cnt = g_cnt[id];
    float pos_cnt = cnt - 1.0f;
    float neg_cnt = (float)BN - cnt;
    float pos_mean = (g_rowsame[i] - dg) / fmaxf(pos_cnt, 1.0f);
    float neg_mean = (g_rowsum[i] - g_rowsame[i]) / fmaxf(neg_cnt, 1.0f);
    float tri = fmaxf(neg_mean - pos_mean + MARGIN, 0.0f);
    bool valid = (pos_cnt > 0.0f) && (neg_cnt > 0.0f);
    float tri_v = valid ? tri : 0.0f;
    float tri_n = valid ? 1.0f : 0.0f;
    #pragma unroll
    for (int o = 16; o > 0; o >>= 1) {
        tri_v += __shfl_xor_sync(0xffffffffu, tri_v, o);
        tri_n += __shfl_xor_sync(0xffffffffu, tri_n, o);
    }
    if ((tid & 31) == 0) {
        atomicAdd(&g_tri[0], tri_v);
        atomicAdd(&g_tri[1], tri_n);
    }
    __syncthreads();
    if (tid < NS) {
        atomicAdd(&g_segv[tid], sh_segv[tid]);
        atomicAdd(&g_segt[tid], sh_segt[tid]);
    }

    __threadfence();
    __syncthreads();
    if (tid == 0)
        sh_last = (atomicAdd(&g_done, 1) == (int)gridDim.x - 1);
    __syncthreads();
    if (!sh_last) return;
    __threadfence();

    // parallel combine: 64 threads, one species each
    float per = 0.f, nv = 0.f;
    if (tid < NS) {
        float cnt2 = g_cnt[tid];
        float sv = g_segv[tid];
        float st = g_segt[tid];
        if (cnt2 >= 2.0f) {
            per = (sv + st) / (2.0f * cnt2);
            nv = 1.0f;
        }
    }
    if (tid < NS) sh_red[tid] = per;
    __syncthreads();
    if (tid < 32) {
        float a = sh_red[tid] + sh_red[tid + 32];
        float b = (tid < NS - 32) ? 0.f : 0.f;   // (all in a)
        float n = nv;
        // nv for tid<32 only covers its own species; gather the upper half's nv
        // via shared as well:
        (void)b;
        #pragma unroll
        for (int o = 16; o > 0; o >>= 1)
            a += __shfl_xor_sync(0xffffffffu, a, o);
        sh_red[tid] = a;   // lane 0 has total per-sum
        (void)n;
    }
    // count valid species in parallel too
    __syncthreads();
    float total_per = sh_red[0];
    if (tid < NS) sh_red[tid] = nv;
    __syncthreads();
    if (tid < 32) {
        float n = sh_red[tid] + sh_red[tid + 32];
        #pragma unroll
        for (int o = 16; o > 0; o >>= 1)
            n += __shfl_xor_sync(0xffffffffu, n, o);
        if (tid == 0) {
            float loss_infonce = total_per / fmaxf(n, 1.0f);
            float loss_triplet = g_tri[0] / fmaxf(g_tri[1], 1.0f);
            out[0] = loss_infonce + loss_triplet;
        }
    }
}

extern "C" void kernel_launch(void* const* d_in, const int* in_sizes, int n_in,
                              void* d_out, int out_size) {
    const float* species = (const float*)d_in[0];
    const float* text    = (const float*)d_in[1];
    const int*   ids     = (const int*)d_in[2];
    float* out = (float*)d_out;

    cudaFuncSetAttribute(blockexp_kernel,
                         cudaFuncAttributeMaxDynamicSharedMemorySize, SMEM_BE);

    setup_kernel<<<1, 1024>>>(ids);
    prep_kernel<<<BN / 8, 256>>>(species, text, ids);
    blockexp_kernel<<<dim3(16, NS), 128, SMEM_BE>>>();
    final_kernel<<<BN / 256, 256>>>(ids, out);
}